// round 1
// baseline (speedup 1.0000x reference)
#include <cuda_runtime.h>
#include <math.h>

// Problem constants
#define HD   1024          // hidden size H
#define K2   2048          // 2*H
#define BB   8             // batch
#define SS   4096          // encoder seq len
#define LL   64            // decoder len
#define M512 (BB*LL)       // 512 fused (b,l) rows

// Scratch (device globals; no allocations allowed)
__device__ float g_Wh[M512 * K2];       // [ (b*64+l), k ]   4 MB
__device__ float g_bh[M512];            // [ (b*64+l) ]
__device__ float g_scores[M512 * SS];   // [ (b*64+l), s ]   8 MB  (becomes weights in-place)
__device__ float g_ctx2[M512 * K2];     // [ (b*64+l), k ]   4 MB

// ---------------------------------------------------------------------------
// bh[b,l] = sum_h bias[h] * hidden[l,b,h]   (one warp per output)
// ---------------------------------------------------------------------------
__global__ __launch_bounds__(256) void k_bh(const float* __restrict__ hidden,
                                            const float* __restrict__ bias) {
    int w = (blockIdx.x * 256 + threadIdx.x) >> 5;   // 0..511
    int lane = threadIdx.x & 31;
    int b = w >> 6, l = w & 63;
    const float* hrow = hidden + (l * BB + b) * HD;
    float s = 0.f;
    for (int h = lane; h < HD; h += 32) s += bias[h] * hrow[h];
    #pragma unroll
    for (int o = 16; o; o >>= 1) s += __shfl_xor_sync(0xffffffffu, s, o);
    if (lane == 0) g_bh[w] = s;
}

// ---------------------------------------------------------------------------
// K1: Wh[m,k] = sum_h hidden_row(m)[h] * W[h,k]
//   M=512 (m=(b,l), row at hidden[(l*8+b)*1024]),  N=2048, K=1024
//   BM=128, BN=64, BK=16, 256 thr, 8x4 micro-tile
// ---------------------------------------------------------------------------
__global__ __launch_bounds__(256) void k1_wh(const float* __restrict__ hidden,
                                             const float* __restrict__ W) {
    __shared__ __align__(16) float As[16][132];   // [k][m]
    __shared__ __align__(16) float Bs[16][68];    // [k][n]
    int m0 = blockIdx.y * 128;
    int n0 = blockIdx.x * 64;
    int t = threadIdx.x, tx = t & 15, ty = t >> 4;
    float c[8][4] = {};
    for (int k0 = 0; k0 < HD; k0 += 16) {
        #pragma unroll
        for (int r = 0; r < 2; r++) {
            int idx = t + r * 256;
            int m = idx >> 2, k4 = (idx & 3) * 4;
            int gm = m0 + m;
            int bb = gm >> 6, ll = gm & 63;
            float4 v = *(const float4*)(hidden + (ll * BB + bb) * HD + k0 + k4);
            As[k4 + 0][m] = v.x; As[k4 + 1][m] = v.y;
            As[k4 + 2][m] = v.z; As[k4 + 3][m] = v.w;
        }
        {
            int kk = t >> 4, n4 = (t & 15) * 4;
            *(float4*)&Bs[kk][n4] = *(const float4*)(W + (k0 + kk) * K2 + n0 + n4);
        }
        __syncthreads();
        #pragma unroll
        for (int kk = 0; kk < 16; kk++) {
            float4 a0 = *(const float4*)&As[kk][ty * 8];
            float4 a1 = *(const float4*)&As[kk][ty * 8 + 4];
            float4 bv = *(const float4*)&Bs[kk][tx * 4];
            float a[8] = {a0.x,a0.y,a0.z,a0.w,a1.x,a1.y,a1.z,a1.w};
            float bb2[4] = {bv.x,bv.y,bv.z,bv.w};
            #pragma unroll
            for (int i = 0; i < 8; i++)
                #pragma unroll
                for (int j = 0; j < 4; j++) c[i][j] += a[i] * bb2[j];
        }
        __syncthreads();
    }
    #pragma unroll
    for (int i = 0; i < 8; i++) {
        float4 v = {c[i][0], c[i][1], c[i][2], c[i][3]};
        *(float4*)(g_Wh + (size_t)(m0 + ty * 8 + i) * K2 + n0 + tx * 4) = v;
    }
}

// ---------------------------------------------------------------------------
// K2: scores_t[(b*64+l), s] = bh[b,l] + sum_k enc[b,s,k] * Wh[(b,l),k]
//   per-batch GEMM: M=4096 (s), N=64 (l), K=2048.  BM=128, BN=64, BK=16.
//   Output stored transposed [l][s] for coalesced softmax.
// ---------------------------------------------------------------------------
__global__ __launch_bounds__(256) void k2_scores(const float* __restrict__ enc) {
    __shared__ __align__(16) float As[16][132];   // enc tile [k][s]
    __shared__ __align__(16) float Bs[16][68];    // Wh  tile [k][l]
    int b = blockIdx.y;
    int s0 = blockIdx.x * 128;
    int t = threadIdx.x, tx = t & 15, ty = t >> 4;
    float c[8][4] = {};
    const float* encb = enc + (size_t)b * SS * K2;
    const float* whb  = g_Wh + (size_t)b * 64 * K2;
    for (int k0 = 0; k0 < K2; k0 += 16) {
        #pragma unroll
        for (int r = 0; r < 2; r++) {
            int idx = t + r * 256;
            int m = idx >> 2, k4 = (idx & 3) * 4;
            float4 v = *(const float4*)(encb + (size_t)(s0 + m) * K2 + k0 + k4);
            As[k4 + 0][m] = v.x; As[k4 + 1][m] = v.y;
            As[k4 + 2][m] = v.z; As[k4 + 3][m] = v.w;
        }
        {
            int n = t >> 2, k4 = (t & 3) * 4;
            float4 v = *(const float4*)(whb + (size_t)n * K2 + k0 + k4);
            Bs[k4 + 0][n] = v.x; Bs[k4 + 1][n] = v.y;
            Bs[k4 + 2][n] = v.z; Bs[k4 + 3][n] = v.w;
        }
        __syncthreads();
        #pragma unroll
        for (int kk = 0; kk < 16; kk++) {
            float4 a0 = *(const float4*)&As[kk][ty * 8];
            float4 a1 = *(const float4*)&As[kk][ty * 8 + 4];
            float4 bv = *(const float4*)&Bs[kk][tx * 4];
            float a[8] = {a0.x,a0.y,a0.z,a0.w,a1.x,a1.y,a1.z,a1.w};
            float bb2[4] = {bv.x,bv.y,bv.z,bv.w};
            #pragma unroll
            for (int i = 0; i < 8; i++)
                #pragma unroll
                for (int j = 0; j < 4; j++) c[i][j] += a[i] * bb2[j];
        }
        __syncthreads();
    }
    #pragma unroll
    for (int j = 0; j < 4; j++) {
        int n = tx * 4 + j;
        float bhv = g_bh[b * 64 + n];
        float4 v0 = {c[0][j] + bhv, c[1][j] + bhv, c[2][j] + bhv, c[3][j] + bhv};
        float4 v1 = {c[4][j] + bhv, c[5][j] + bhv, c[6][j] + bhv, c[7][j] + bhv};
        float* dst = g_scores + (size_t)(b * 64 + n) * SS + s0 + ty * 8;
        *(float4*)dst = v0;
        *(float4*)(dst + 4) = v1;
    }
}

// ---------------------------------------------------------------------------
// K3: softmax over s for each (b,l) row (contiguous, 4096 elems).
//     Writes weights in-place (for K4) and to d_out in [B,S,L] layout.
// ---------------------------------------------------------------------------
__global__ __launch_bounds__(256) void k3_softmax(float* __restrict__ out_w) {
    int row = blockIdx.x;                 // (b*64+l)
    float* p = g_scores + (size_t)row * SS;
    int t = threadIdx.x;
    __shared__ float red[256];
    float v[16];
    float m = -1e30f;
    #pragma unroll
    for (int i = 0; i < 16; i++) { v[i] = p[t + i * 256]; m = fmaxf(m, v[i]); }
    red[t] = m; __syncthreads();
    #pragma unroll
    for (int o = 128; o; o >>= 1) {
        if (t < o) red[t] = fmaxf(red[t], red[t + o]);
        __syncthreads();
    }
    m = red[0]; __syncthreads();
    float s = 0.f;
    #pragma unroll
    for (int i = 0; i < 16; i++) { v[i] = expf(v[i] - m); s += v[i]; }
    red[t] = s; __syncthreads();
    #pragma unroll
    for (int o = 128; o; o >>= 1) {
        if (t < o) red[t] += red[t + o];
        __syncthreads();
    }
    float inv = 1.f / red[0];
    int b = row >> 6, l = row & 63;
    #pragma unroll
    for (int i = 0; i < 16; i++) {
        float w = v[i] * inv;
        int si = t + i * 256;
        p[si] = w;                                        // in-place for K4
        out_w[((size_t)b * SS + si) * LL + l] = w;        // [B,S,L] output
    }
}

// ---------------------------------------------------------------------------
// K4: ctx2[(b*64+l), k] = sum_s weights_t[(b*64+l), s] * enc[b,s,k]
//   per-batch GEMM: M=64 (l), N=2048 (k), K=4096 (s). BM=64, BN=128, BK=16.
// ---------------------------------------------------------------------------
__global__ __launch_bounds__(256) void k4_ctx2(const float* __restrict__ enc) {
    __shared__ __align__(16) float As[16][68];    // wt tile  [s][l]
    __shared__ __align__(16) float Bs[16][132];   // enc tile [s][k]
    int b = blockIdx.y;
    int n0 = blockIdx.x * 128;
    int t = threadIdx.x, tx = t & 15, ty = t >> 4;
    float c[4][8] = {};
    const float* wtb  = g_scores + (size_t)b * 64 * SS;
    const float* encb = enc + (size_t)b * SS * K2;
    for (int s0 = 0; s0 < SS; s0 += 16) {
        {
            int m = t >> 2, k4 = (t & 3) * 4;
            float4 v = *(const float4*)(wtb + (size_t)m * SS + s0 + k4);
            As[k4 + 0][m] = v.x; As[k4 + 1][m] = v.y;
            As[k4 + 2][m] = v.z; As[k4 + 3][m] = v.w;
        }
        #pragma unroll
        for (int r = 0; r < 2; r++) {
            int idx = t + r * 256;
            int kk = idx >> 5, n4 = (idx & 31) * 4;
            *(float4*)&Bs[kk][n4] =
                *(const float4*)(encb + (size_t)(s0 + kk) * K2 + n0 + n4);
        }
        __syncthreads();
        #pragma unroll
        for (int kk = 0; kk < 16; kk++) {
            float4 av = *(const float4*)&As[kk][ty * 4];
            float4 b0 = *(const float4*)&Bs[kk][tx * 8];
            float4 b1 = *(const float4*)&Bs[kk][tx * 8 + 4];
            float a[4] = {av.x, av.y, av.z, av.w};
            float bb2[8] = {b0.x,b0.y,b0.z,b0.w,b1.x,b1.y,b1.z,b1.w};
            #pragma unroll
            for (int i = 0; i < 4; i++)
                #pragma unroll
                for (int j = 0; j < 8; j++) c[i][j] += a[i] * bb2[j];
        }
        __syncthreads();
    }
    #pragma unroll
    for (int i = 0; i < 4; i++) {
        float* dst = g_ctx2 + (size_t)(b * 64 + ty * 4 + i) * K2 + n0 + tx * 8;
        float4 v0 = {c[i][0], c[i][1], c[i][2], c[i][3]};
        float4 v1 = {c[i][4], c[i][5], c[i][6], c[i][7]};
        *(float4*)dst = v0;
        *(float4*)(dst + 4) = v1;
    }
}

// ---------------------------------------------------------------------------
// K5: context[(b*64+l), h] = bias[h] + sum_k ctx2[(b,l),k] * W[h,k]
//   M=512, N=1024, K=2048. BM=64, BN=64, BK=16, 4x4 micro-tile.
// ---------------------------------------------------------------------------
__global__ __launch_bounds__(256) void k5_out(const float* __restrict__ W,
                                              const float* __restrict__ bias,
                                              float* __restrict__ out) {
    __shared__ __align__(16) float As[16][68];    // [k][m]
    __shared__ __align__(16) float Bs[16][68];    // [k][n]
    int m0 = blockIdx.y * 64;
    int n0 = blockIdx.x * 64;
    int t = threadIdx.x, tx = t & 15, ty = t >> 4;
    float c[4][4] = {};
    for (int k0 = 0; k0 < K2; k0 += 16) {
        {
            int m = t >> 2, k4 = (t & 3) * 4;
            float4 v = *(const float4*)(g_ctx2 + (size_t)(m0 + m) * K2 + k0 + k4);
            As[k4 + 0][m] = v.x; As[k4 + 1][m] = v.y;
            As[k4 + 2][m] = v.z; As[k4 + 3][m] = v.w;
        }
        {
            int n = t >> 2, k4 = (t & 3) * 4;
            float4 v = *(const float4*)(W + (size_t)(n0 + n) * K2 + k0 + k4);
            Bs[k4 + 0][n] = v.x; Bs[k4 + 1][n] = v.y;
            Bs[k4 + 2][n] = v.z; Bs[k4 + 3][n] = v.w;
        }
        __syncthreads();
        #pragma unroll
        for (int kk = 0; kk < 16; kk++) {
            float4 av = *(const float4*)&As[kk][ty * 4];
            float4 bv = *(const float4*)&Bs[kk][tx * 4];
            float a[4] = {av.x, av.y, av.z, av.w};
            float bb2[4] = {bv.x, bv.y, bv.z, bv.w};
            #pragma unroll
            for (int i = 0; i < 4; i++)
                #pragma unroll
                for (int j = 0; j < 4; j++) c[i][j] += a[i] * bb2[j];
        }
        __syncthreads();
    }
    float4 bv = *(const float4*)(bias + n0 + tx * 4);
    #pragma unroll
    for (int i = 0; i < 4; i++) {
        float4 v = {c[i][0] + bv.x, c[i][1] + bv.y, c[i][2] + bv.z, c[i][3] + bv.w};
        *(float4*)(out + (size_t)(m0 + ty * 4 + i) * HD + n0 + tx * 4) = v;
    }
}

// ---------------------------------------------------------------------------
extern "C" void kernel_launch(void* const* d_in, const int* in_sizes, int n_in,
                              void* d_out, int out_size) {
    (void)in_sizes; (void)n_in; (void)out_size;
    const float* hidden = (const float*)d_in[0];   // [L,B,H]
    const float* enc    = (const float*)d_in[1];   // [B,S,2H]
    const float* W      = (const float*)d_in[2];   // [H,2H]
    const float* bias   = (const float*)d_in[3];   // [H]
    float* out_ctx = (float*)d_out;                       // [B,L,H]
    float* out_w   = (float*)d_out + (size_t)BB * LL * HD; // [B,S,L]

    k_bh<<<64, 256>>>(hidden, bias);
    k1_wh<<<dim3(32, 4), 256>>>(hidden, W);
    k2_scores<<<dim3(32, 8), 256>>>(enc);
    k3_softmax<<<512, 256>>>(out_w);
    k4_ctx2<<<dim3(16, 8), 256>>>(enc);
    k5_out<<<dim3(16, 8), 256>>>(W, bias, out_ctx);
}

// round 2
// speedup vs baseline: 1.0002x; 1.0002x over previous
#include <cuda_runtime.h>
#include <math.h>

// Problem constants
#define HD   1024          // hidden size H
#define K2   2048          // 2*H
#define BB   8             // batch
#define SS   4096          // encoder seq len
#define LL   64            // decoder len
#define M512 (BB*LL)       // 512 fused (b,l) rows

// Scratch (device globals; no allocations allowed)
__device__ float g_Wh[M512 * K2];       // [ (b*64+l), k ]   4 MB
__device__ float g_bh[M512];            // [ (b*64+l) ]
__device__ float g_scores[M512 * SS];   // [ (b*64+l), s ]   8 MB  (becomes weights in-place)
__device__ float g_ctx2[M512 * K2];     // [ (b*64+l), k ]   4 MB

// ---------------------------------------------------------------------------
// bh[b,l] = sum_h bias[h] * hidden[l,b,h]   (one warp per output)
// ---------------------------------------------------------------------------
__global__ __launch_bounds__(256) void k_bh(const float* __restrict__ hidden,
                                            const float* __restrict__ bias) {
    int w = (blockIdx.x * 256 + threadIdx.x) >> 5;   // 0..511
    int lane = threadIdx.x & 31;
    int b = w >> 6, l = w & 63;
    const float* hrow = hidden + (l * BB + b) * HD;
    float s = 0.f;
    for (int h = lane; h < HD; h += 32) s += bias[h] * hrow[h];
    #pragma unroll
    for (int o = 16; o; o >>= 1) s += __shfl_xor_sync(0xffffffffu, s, o);
    if (lane == 0) g_bh[w] = s;
}

// ---------------------------------------------------------------------------
// K1: Wh[m,k] = sum_h hidden_row(m)[h] * W[h,k]
//   M=512 (m=(b,l), row at hidden[(l*8+b)*1024]),  N=2048, K=1024
//   BM=128, BN=64, BK=16, 256 thr, 8x4 micro-tile
// ---------------------------------------------------------------------------
__global__ __launch_bounds__(256) void k1_wh(const float* __restrict__ hidden,
                                             const float* __restrict__ W) {
    __shared__ __align__(16) float As[16][132];   // [k][m]
    __shared__ __align__(16) float Bs[16][68];    // [k][n]
    int m0 = blockIdx.y * 128;
    int n0 = blockIdx.x * 64;
    int t = threadIdx.x, tx = t & 15, ty = t >> 4;
    float c[8][4] = {};
    for (int k0 = 0; k0 < HD; k0 += 16) {
        #pragma unroll
        for (int r = 0; r < 2; r++) {
            int idx = t + r * 256;
            int m = idx >> 2, k4 = (idx & 3) * 4;
            int gm = m0 + m;
            int bb = gm >> 6, ll = gm & 63;
            float4 v = *(const float4*)(hidden + (ll * BB + bb) * HD + k0 + k4);
            As[k4 + 0][m] = v.x; As[k4 + 1][m] = v.y;
            As[k4 + 2][m] = v.z; As[k4 + 3][m] = v.w;
        }
        {
            int kk = t >> 4, n4 = (t & 15) * 4;
            *(float4*)&Bs[kk][n4] = *(const float4*)(W + (k0 + kk) * K2 + n0 + n4);
        }
        __syncthreads();
        #pragma unroll
        for (int kk = 0; kk < 16; kk++) {
            float4 a0 = *(const float4*)&As[kk][ty * 8];
            float4 a1 = *(const float4*)&As[kk][ty * 8 + 4];
            float4 bv = *(const float4*)&Bs[kk][tx * 4];
            float a[8] = {a0.x,a0.y,a0.z,a0.w,a1.x,a1.y,a1.z,a1.w};
            float bb2[4] = {bv.x,bv.y,bv.z,bv.w};
            #pragma unroll
            for (int i = 0; i < 8; i++)
                #pragma unroll
                for (int j = 0; j < 4; j++) c[i][j] += a[i] * bb2[j];
        }
        __syncthreads();
    }
    #pragma unroll
    for (int i = 0; i < 8; i++) {
        float4 v = {c[i][0], c[i][1], c[i][2], c[i][3]};
        *(float4*)(g_Wh + (size_t)(m0 + ty * 8 + i) * K2 + n0 + tx * 4) = v;
    }
}

// ---------------------------------------------------------------------------
// K2: scores_t[(b*64+l), s] = bh[b,l] + sum_k enc[b,s,k] * Wh[(b,l),k]
//   per-batch GEMM: M=4096 (s), N=64 (l), K=2048.  BM=128, BN=64, BK=16.
//   Output stored transposed [l][s] for coalesced softmax.
// ---------------------------------------------------------------------------
__global__ __launch_bounds__(256) void k2_scores(const float* __restrict__ enc) {
    __shared__ __align__(16) float As[16][132];   // enc tile [k][s]
    __shared__ __align__(16) float Bs[16][68];    // Wh  tile [k][l]
    int b = blockIdx.y;
    int s0 = blockIdx.x * 128;
    int t = threadIdx.x, tx = t & 15, ty = t >> 4;
    float c[8][4] = {};
    const float* encb = enc + (size_t)b * SS * K2;
    const float* whb  = g_Wh + (size_t)b * 64 * K2;
    for (int k0 = 0; k0 < K2; k0 += 16) {
        #pragma unroll
        for (int r = 0; r < 2; r++) {
            int idx = t + r * 256;
            int m = idx >> 2, k4 = (idx & 3) * 4;
            float4 v = *(const float4*)(encb + (size_t)(s0 + m) * K2 + k0 + k4);
            As[k4 + 0][m] = v.x; As[k4 + 1][m] = v.y;
            As[k4 + 2][m] = v.z; As[k4 + 3][m] = v.w;
        }
        {
            int n = t >> 2, k4 = (t & 3) * 4;
            float4 v = *(const float4*)(whb + (size_t)n * K2 + k0 + k4);
            Bs[k4 + 0][n] = v.x; Bs[k4 + 1][n] = v.y;
            Bs[k4 + 2][n] = v.z; Bs[k4 + 3][n] = v.w;
        }
        __syncthreads();
        #pragma unroll
        for (int kk = 0; kk < 16; kk++) {
            float4 a0 = *(const float4*)&As[kk][ty * 8];
            float4 a1 = *(const float4*)&As[kk][ty * 8 + 4];
            float4 bv = *(const float4*)&Bs[kk][tx * 4];
            float a[8] = {a0.x,a0.y,a0.z,a0.w,a1.x,a1.y,a1.z,a1.w};
            float bb2[4] = {bv.x,bv.y,bv.z,bv.w};
            #pragma unroll
            for (int i = 0; i < 8; i++)
                #pragma unroll
                for (int j = 0; j < 4; j++) c[i][j] += a[i] * bb2[j];
        }
        __syncthreads();
    }
    #pragma unroll
    for (int j = 0; j < 4; j++) {
        int n = tx * 4 + j;
        float bhv = g_bh[b * 64 + n];
        float4 v0 = {c[0][j] + bhv, c[1][j] + bhv, c[2][j] + bhv, c[3][j] + bhv};
        float4 v1 = {c[4][j] + bhv, c[5][j] + bhv, c[6][j] + bhv, c[7][j] + bhv};
        float* dst = g_scores + (size_t)(b * 64 + n) * SS + s0 + ty * 8;
        *(float4*)dst = v0;
        *(float4*)(dst + 4) = v1;
    }
}

// ---------------------------------------------------------------------------
// K3: softmax over s for each (b,l) row (contiguous, 4096 elems).
//     Writes weights in-place (for K4) and to d_out in [B,S,L] layout.
// ---------------------------------------------------------------------------
__global__ __launch_bounds__(256) void k3_softmax(float* __restrict__ out_w) {
    int row = blockIdx.x;                 // (b*64+l)
    float* p = g_scores + (size_t)row * SS;
    int t = threadIdx.x;
    __shared__ float red[256];
    float v[16];
    float m = -1e30f;
    #pragma unroll
    for (int i = 0; i < 16; i++) { v[i] = p[t + i * 256]; m = fmaxf(m, v[i]); }
    red[t] = m; __syncthreads();
    #pragma unroll
    for (int o = 128; o; o >>= 1) {
        if (t < o) red[t] = fmaxf(red[t], red[t + o]);
        __syncthreads();
    }
    m = red[0]; __syncthreads();
    float s = 0.f;
    #pragma unroll
    for (int i = 0; i < 16; i++) { v[i] = expf(v[i] - m); s += v[i]; }
    red[t] = s; __syncthreads();
    #pragma unroll
    for (int o = 128; o; o >>= 1) {
        if (t < o) red[t] += red[t + o];
        __syncthreads();
    }
    float inv = 1.f / red[0];
    int b = row >> 6, l = row & 63;
    #pragma unroll
    for (int i = 0; i < 16; i++) {
        float w = v[i] * inv;
        int si = t + i * 256;
        p[si] = w;                                        // in-place for K4
        out_w[((size_t)b * SS + si) * LL + l] = w;        // [B,S,L] output
    }
}

// ---------------------------------------------------------------------------
// K4: ctx2[(b*64+l), k] = sum_s weights_t[(b*64+l), s] * enc[b,s,k]
//   per-batch GEMM: M=64 (l), N=2048 (k), K=4096 (s). BM=64, BN=128, BK=16.
// ---------------------------------------------------------------------------
__global__ __launch_bounds__(256) void k4_ctx2(const float* __restrict__ enc) {
    __shared__ __align__(16) float As[16][68];    // wt tile  [s][l]
    __shared__ __align__(16) float Bs[16][132];   // enc tile [s][k]
    int b = blockIdx.y;
    int n0 = blockIdx.x * 128;
    int t = threadIdx.x, tx = t & 15, ty = t >> 4;
    float c[4][8] = {};
    const float* wtb  = g_scores + (size_t)b * 64 * SS;
    const float* encb = enc + (size_t)b * SS * K2;
    for (int s0 = 0; s0 < SS; s0 += 16) {
        {
            int m = t >> 2, k4 = (t & 3) * 4;
            float4 v = *(const float4*)(wtb + (size_t)m * SS + s0 + k4);
            As[k4 + 0][m] = v.x; As[k4 + 1][m] = v.y;
            As[k4 + 2][m] = v.z; As[k4 + 3][m] = v.w;
        }
        #pragma unroll
        for (int r = 0; r < 2; r++) {
            int idx = t + r * 256;
            int kk = idx >> 5, n4 = (idx & 31) * 4;
            *(float4*)&Bs[kk][n4] =
                *(const float4*)(encb + (size_t)(s0 + kk) * K2 + n0 + n4);
        }
        __syncthreads();
        #pragma unroll
        for (int kk = 0; kk < 16; kk++) {
            float4 av = *(const float4*)&As[kk][ty * 4];
            float4 b0 = *(const float4*)&Bs[kk][tx * 8];
            float4 b1 = *(const float4*)&Bs[kk][tx * 8 + 4];
            float a[4] = {av.x, av.y, av.z, av.w};
            float bb2[8] = {b0.x,b0.y,b0.z,b0.w,b1.x,b1.y,b1.z,b1.w};
            #pragma unroll
            for (int i = 0; i < 4; i++)
                #pragma unroll
                for (int j = 0; j < 8; j++) c[i][j] += a[i] * bb2[j];
        }
        __syncthreads();
    }
    #pragma unroll
    for (int i = 0; i < 4; i++) {
        float* dst = g_ctx2 + (size_t)(b * 64 + ty * 4 + i) * K2 + n0 + tx * 8;
        float4 v0 = {c[i][0], c[i][1], c[i][2], c[i][3]};
        float4 v1 = {c[i][4], c[i][5], c[i][6], c[i][7]};
        *(float4*)dst = v0;
        *(float4*)(dst + 4) = v1;
    }
}

// ---------------------------------------------------------------------------
// K5: context[(b*64+l), h] = bias[h] + sum_k ctx2[(b,l),k] * W[h,k]
//   M=512, N=1024, K=2048. BM=64, BN=64, BK=16, 4x4 micro-tile.
// ---------------------------------------------------------------------------
__global__ __launch_bounds__(256) void k5_out(const float* __restrict__ W,
                                              const float* __restrict__ bias,
                                              float* __restrict__ out) {
    __shared__ __align__(16) float As[16][68];    // [k][m]
    __shared__ __align__(16) float Bs[16][68];    // [k][n]
    int m0 = blockIdx.y * 64;
    int n0 = blockIdx.x * 64;
    int t = threadIdx.x, tx = t & 15, ty = t >> 4;
    float c[4][4] = {};
    for (int k0 = 0; k0 < K2; k0 += 16) {
        {
            int m = t >> 2, k4 = (t & 3) * 4;
            float4 v = *(const float4*)(g_ctx2 + (size_t)(m0 + m) * K2 + k0 + k4);
            As[k4 + 0][m] = v.x; As[k4 + 1][m] = v.y;
            As[k4 + 2][m] = v.z; As[k4 + 3][m] = v.w;
        }
        {
            int n = t >> 2, k4 = (t & 3) * 4;
            float4 v = *(const float4*)(W + (size_t)(n0 + n) * K2 + k0 + k4);
            Bs[k4 + 0][n] = v.x; Bs[k4 + 1][n] = v.y;
            Bs[k4 + 2][n] = v.z; Bs[k4 + 3][n] = v.w;
        }
        __syncthreads();
        #pragma unroll
        for (int kk = 0; kk < 16; kk++) {
            float4 av = *(const float4*)&As[kk][ty * 4];
            float4 bv = *(const float4*)&Bs[kk][tx * 4];
            float a[4] = {av.x, av.y, av.z, av.w};
            float bb2[4] = {bv.x, bv.y, bv.z, bv.w};
            #pragma unroll
            for (int i = 0; i < 4; i++)
                #pragma unroll
                for (int j = 0; j < 4; j++) c[i][j] += a[i] * bb2[j];
        }
        __syncthreads();
    }
    float4 bv = *(const float4*)(bias + n0 + tx * 4);
    #pragma unroll
    for (int i = 0; i < 4; i++) {
        float4 v = {c[i][0] + bv.x, c[i][1] + bv.y, c[i][2] + bv.z, c[i][3] + bv.w};
        *(float4*)(out + (size_t)(m0 + ty * 4 + i) * HD + n0 + tx * 4) = v;
    }
}

// ---------------------------------------------------------------------------
extern "C" void kernel_launch(void* const* d_in, const int* in_sizes, int n_in,
                              void* d_out, int out_size) {
    (void)in_sizes; (void)n_in; (void)out_size;
    const float* hidden = (const float*)d_in[0];   // [L,B,H]
    const float* enc    = (const float*)d_in[1];   // [B,S,2H]
    const float* W      = (const float*)d_in[2];   // [H,2H]
    const float* bias   = (const float*)d_in[3];   // [H]
    float* out_ctx = (float*)d_out;                       // [B,L,H]
    float* out_w   = (float*)d_out + (size_t)BB * LL * HD; // [B,S,L]

    k_bh<<<64, 256>>>(hidden, bias);
    k1_wh<<<dim3(32, 4), 256>>>(hidden, W);
    k2_scores<<<dim3(32, 8), 256>>>(enc);
    k3_softmax<<<512, 256>>>(out_w);
    k4_ctx2<<<dim3(16, 8), 256>>>(enc);
    k5_out<<<dim3(16, 8), 256>>>(W, bias, out_ctx);
}

// round 4
// speedup vs baseline: 1.9110x; 1.9106x over previous
#include <cuda_runtime.h>
#include <cuda_bf16.h>
#include <math.h>
#include <stdint.h>

#define HD   1024
#define K2   2048
#define BB   8
#define SS   4096
#define LL   64
#define M512 (BB*LL)

// ---- device scratch ----
__device__ __nv_bfloat16 g_Wh_h[M512 * K2];
__device__ __nv_bfloat16 g_Wh_l[M512 * K2];
__device__ float         g_bh[M512];
__device__ float         g_scores[(size_t)M512 * SS];
__device__ __nv_bfloat16 g_w_h[(size_t)M512 * SS];
__device__ __nv_bfloat16 g_w_l[(size_t)M512 * SS];
__device__ __nv_bfloat16 g_c2_h[M512 * K2];
__device__ __nv_bfloat16 g_c2_l[M512 * K2];

// ---- helpers ----
__device__ __forceinline__ uint32_t smem_u32(const void* p) {
    uint32_t a;
    asm("{ .reg .u64 t; cvta.to.shared.u64 t, %1; cvt.u32.u64 %0, t; }" : "=r"(a) : "l"(p));
    return a;
}
// hi/lo bf16 split of an fp32 pair (x0 -> low half)
__device__ __forceinline__ void split2(float x0, float x1, uint32_t& h, uint32_t& l) {
    __nv_bfloat162 hh = __floats2bfloat162_rn(x0, x1);
    h = *(uint32_t*)&hh;
    float h0 = __uint_as_float(h << 16);
    float h1 = __uint_as_float(h & 0xFFFF0000u);
    __nv_bfloat162 ll = __floats2bfloat162_rn(x0 - h0, x1 - h1);
    l = *(uint32_t*)&ll;
}
__device__ __forceinline__ void mma_bf16(float* d, const uint32_t* a, uint32_t b0, uint32_t b1) {
    asm volatile(
        "mma.sync.aligned.m16n8k16.row.col.f32.bf16.bf16.f32 "
        "{%0,%1,%2,%3}, {%4,%5,%6,%7}, {%8,%9}, {%0,%1,%2,%3};"
        : "+f"(d[0]), "+f"(d[1]), "+f"(d[2]), "+f"(d[3])
        : "r"(a[0]), "r"(a[1]), "r"(a[2]), "r"(a[3]), "r"(b0), "r"(b1));
}
__device__ __forceinline__ void ldmx4(uint32_t* r, uint32_t addr) {
    asm volatile("ldmatrix.sync.aligned.m8n8.x4.shared.b16 {%0,%1,%2,%3}, [%4];"
                 : "=r"(r[0]), "=r"(r[1]), "=r"(r[2]), "=r"(r[3]) : "r"(addr));
}
// byte offset of (row l, k-offset ko[0..127]) inside a 32KB staged chunk:
// two 8KB sub-tiles (64 rows x 128B), SW128-style swizzle
__device__ __forceinline__ uint32_t bofs(int l, int ko) {
    return ((uint32_t)(ko >> 6) << 13) +
           ((((uint32_t)l << 7) + (uint32_t)((ko & 63) << 1)) ^ (uint32_t)((l & 7) << 4));
}

// ---------------------------------------------------------------------------
__global__ __launch_bounds__(256) void k_bh(const float* __restrict__ hidden,
                                            const float* __restrict__ bias) {
    int w = (blockIdx.x * 256 + threadIdx.x) >> 5;
    int lane = threadIdx.x & 31;
    int b = w >> 6, l = w & 63;
    const float* hrow = hidden + (l * BB + b) * HD;
    float s = 0.f;
    for (int h = lane; h < HD; h += 32) s += bias[h] * hrow[h];
    #pragma unroll
    for (int o = 16; o; o >>= 1) s += __shfl_xor_sync(0xffffffffu, s, o);
    if (lane == 0) g_bh[w] = s;
}

// ---------------------------------------------------------------------------
// K1 (mma): Wh[m,n] = sum_h hidden_row(m)[h] * W[h,n]; emit bf16 hi/lo.
// grid (32,4), 256thr; warp tile 16m x 64n; K=1024.
// ---------------------------------------------------------------------------
__global__ __launch_bounds__(256) void k1_mma(const float* __restrict__ hidden,
                                              const float* __restrict__ W) {
    const int tid = threadIdx.x, w = tid >> 5, lane = tid & 31;
    const int grp = lane >> 2, tig = lane & 3;
    const int m0 = blockIdx.y * 128 + w * 16;
    const int n0 = blockIdx.x * 64;
    int mA = m0 + grp, mB = mA + 8;
    const float* row0 = hidden + ((size_t)((mA & 63) * BB + (mA >> 6))) * HD;
    const float* row1 = hidden + ((size_t)((mB & 63) * BB + (mB >> 6))) * HD;

    float d[8][4];
    #pragma unroll
    for (int i = 0; i < 8; i++) { d[i][0]=d[i][1]=d[i][2]=d[i][3]=0.f; }

    for (int k0 = 0; k0 < HD; k0 += 16) {
        float2 v0 = *(const float2*)(row0 + k0 + tig * 2);
        float2 v2 = *(const float2*)(row0 + k0 + tig * 2 + 8);
        float2 v1 = *(const float2*)(row1 + k0 + tig * 2);
        float2 v3 = *(const float2*)(row1 + k0 + tig * 2 + 8);
        uint32_t ah[4], al[4];
        split2(v0.x, v0.y, ah[0], al[0]);
        split2(v1.x, v1.y, ah[1], al[1]);
        split2(v2.x, v2.y, ah[2], al[2]);
        split2(v3.x, v3.y, ah[3], al[3]);
        #pragma unroll
        for (int nt = 0; nt < 8; nt++) {
            const float* wp = W + (size_t)(k0 + 2 * tig) * K2 + n0 + nt * 8 + grp;
            uint32_t bh0, bl0, bh1, bl1;
            split2(wp[0], wp[K2], bh0, bl0);
            split2(wp[8 * K2], wp[9 * K2], bh1, bl1);
            mma_bf16(d[nt], ah, bh0, bh1);
            mma_bf16(d[nt], al, bh0, bh1);
            mma_bf16(d[nt], ah, bl0, bl1);
        }
    }
    #pragma unroll
    for (int nt = 0; nt < 8; nt++) {
        int np = n0 + nt * 8 + tig * 2;
        uint32_t h01, l01, h23, l23;
        split2(d[nt][0], d[nt][1], h01, l01);
        split2(d[nt][2], d[nt][3], h23, l23);
        *(uint32_t*)(g_Wh_h + (size_t)mA * K2 + np) = h01;
        *(uint32_t*)(g_Wh_l + (size_t)mA * K2 + np) = l01;
        *(uint32_t*)(g_Wh_h + (size_t)mB * K2 + np) = h23;
        *(uint32_t*)(g_Wh_l + (size_t)mB * K2 + np) = l23;
    }
}

// ---------------------------------------------------------------------------
// K2 (mma): scores[l, s] = bh[l] + sum_k enc[s,k] * Wh[l,k]
// grid (16, 8), 512thr, 16 warps x 16 s-rows; K=2048, chunk=128 double-buffered.
// ---------------------------------------------------------------------------
__global__ __launch_bounds__(512) void k2_mma(const float* __restrict__ enc) {
    extern __shared__ __align__(128) uint8_t sm[];
    const int tid = threadIdx.x, w = tid >> 5, lane = tid & 31;
    const int grp = lane >> 2, tig = lane & 3;
    const int b = blockIdx.y;
    const int sW = blockIdx.x * 256 + w * 16;
    uint32_t sbase = smem_u32(sm);
    const float* encb = enc + (size_t)b * SS * K2;
    const __nv_bfloat16* Bh = g_Wh_h + (size_t)b * 64 * K2;
    const __nv_bfloat16* Bl = g_Wh_l + (size_t)b * 64 * K2;

    const int q0 = tid, q1 = tid + 512;
    const int l0q = q0 >> 4, ko0q = (q0 & 15) * 8;
    const int l1q = q1 >> 4, ko1q = (q1 & 15) * 8;

    { // prologue: chunk 0 -> buf 0
        uint4 a = *(const uint4*)(Bh + (size_t)l0q * K2 + ko0q);
        uint4 bq = *(const uint4*)(Bh + (size_t)l1q * K2 + ko1q);
        uint4 cq = *(const uint4*)(Bl + (size_t)l0q * K2 + ko0q);
        uint4 dq = *(const uint4*)(Bl + (size_t)l1q * K2 + ko1q);
        *(uint4*)(sm + bofs(l0q, ko0q)) = a;
        *(uint4*)(sm + bofs(l1q, ko1q)) = bq;
        *(uint4*)(sm + 16384 + bofs(l0q, ko0q)) = cq;
        *(uint4*)(sm + 16384 + bofs(l1q, ko1q)) = dq;
    }
    __syncthreads();

    float d[8][4];
    #pragma unroll
    for (int i = 0; i < 8; i++) { d[i][0]=d[i][1]=d[i][2]=d[i][3]=0.f; }

    const float* arow = encb + (size_t)(sW + grp) * K2 + tig * 2;

    for (int c = 0; c < 16; c++) {
        int p = c & 1;
        uint4 ph0, ph1, pl0, pl1;
        if (c < 15) {
            int kb = (c + 1) * 128;
            ph0 = *(const uint4*)(Bh + (size_t)l0q * K2 + kb + ko0q);
            ph1 = *(const uint4*)(Bh + (size_t)l1q * K2 + kb + ko1q);
            pl0 = *(const uint4*)(Bl + (size_t)l0q * K2 + kb + ko0q);
            pl1 = *(const uint4*)(Bl + (size_t)l1q * K2 + kb + ko1q);
        }
        #pragma unroll
        for (int ks = 0; ks < 8; ks++) {
            const float* ap = arow + c * 128 + ks * 16;
            float2 v0 = *(const float2*)(ap);
            float2 v2 = *(const float2*)(ap + 8);
            float2 v1 = *(const float2*)(ap + 8 * K2);
            float2 v3 = *(const float2*)(ap + 8 * K2 + 8);
            uint32_t ah[4], al[4];
            split2(v0.x, v0.y, ah[0], al[0]);
            split2(v1.x, v1.y, ah[1], al[1]);
            split2(v2.x, v2.y, ah[2], al[2]);
            split2(v3.x, v3.y, ah[3], al[3]);
            int kol = ks * 16 + (lane & 8);
            #pragma unroll
            for (int np = 0; np < 4; np++) {
                int lr = np * 16 + (lane & 7) + ((lane >> 1) & 8);
                uint32_t addr = sbase + (uint32_t)p * 32768 + bofs(lr, kol);
                uint32_t bh4[4], bl4[4];
                ldmx4(bh4, addr);
                ldmx4(bl4, addr + 16384);
                mma_bf16(d[2*np],   ah, bh4[0], bh4[1]);
                mma_bf16(d[2*np],   al, bh4[0], bh4[1]);
                mma_bf16(d[2*np],   ah, bl4[0], bl4[1]);
                mma_bf16(d[2*np+1], ah, bh4[2], bh4[3]);
                mma_bf16(d[2*np+1], al, bh4[2], bh4[3]);
                mma_bf16(d[2*np+1], ah, bl4[2], bl4[3]);
            }
        }
        if (c < 15) {
            __syncthreads();
            uint32_t bo = (uint32_t)(p ^ 1) * 32768;
            *(uint4*)(sm + bo + bofs(l0q, ko0q)) = ph0;
            *(uint4*)(sm + bo + bofs(l1q, ko1q)) = ph1;
            *(uint4*)(sm + bo + 16384 + bofs(l0q, ko0q)) = pl0;
            *(uint4*)(sm + bo + 16384 + bofs(l1q, ko1q)) = pl1;
            __syncthreads();
        }
    }
    #pragma unroll
    for (int nt = 0; nt < 8; nt++) {
        int li = nt * 8 + tig * 2;
        float b0v = g_bh[b * 64 + li], b1v = g_bh[b * 64 + li + 1];
        size_t r0 = (size_t)(b * 64 + li) * SS, r1 = r0 + SS;
        int sl = sW + grp;
        g_scores[r0 + sl]     = d[nt][0] + b0v;
        g_scores[r1 + sl]     = d[nt][1] + b1v;
        g_scores[r0 + sl + 8] = d[nt][2] + b0v;
        g_scores[r1 + sl + 8] = d[nt][3] + b1v;
    }
}

// ---------------------------------------------------------------------------
// K3: softmax; emit out_w [B,S,L] fp32 and weights bf16 hi/lo
// ---------------------------------------------------------------------------
__global__ __launch_bounds__(256) void k3_softmax(float* __restrict__ out_w) {
    int row = blockIdx.x;
    const float* p = g_scores + (size_t)row * SS;
    int t = threadIdx.x;
    __shared__ float red[256];
    float v[16];
    float m = -1e30f;
    #pragma unroll
    for (int i = 0; i < 16; i++) { v[i] = p[t + i * 256]; m = fmaxf(m, v[i]); }
    red[t] = m; __syncthreads();
    #pragma unroll
    for (int o = 128; o; o >>= 1) { if (t < o) red[t] = fmaxf(red[t], red[t + o]); __syncthreads(); }
    m = red[0]; __syncthreads();
    float s = 0.f;
    #pragma unroll
    for (int i = 0; i < 16; i++) { v[i] = expf(v[i] - m); s += v[i]; }
    red[t] = s; __syncthreads();
    #pragma unroll
    for (int o = 128; o; o >>= 1) { if (t < o) red[t] += red[t + o]; __syncthreads(); }
    float inv = 1.f / red[0];
    int b = row >> 6, l = row & 63;
    #pragma unroll
    for (int i = 0; i < 16; i += 2) {
        int si = t * 2 + i * 256;   // pairs: thread handles 2 consecutive
        float w0 = p[si] , w1 = p[si + 1];
        w0 = expf(w0 - m) * inv;  w1 = expf(w1 - m) * inv;
        out_w[((size_t)b * SS + si) * LL + l] = w0;
        out_w[((size_t)b * SS + si + 1) * LL + l] = w1;
        uint32_t h, lo2;
        split2(w0, w1, h, lo2);
        *(uint32_t*)(g_w_h + (size_t)row * SS + si) = h;
        *(uint32_t*)(g_w_l + (size_t)row * SS + si) = lo2;
    }
}

// ---------------------------------------------------------------------------
// K4 (mma): ctx2[l, k] = sum_s w[l,s] * enc[s,k]; emit bf16 hi/lo
// grid (16, 8), 512thr, 16 warps (8 k-groups x 2 s-halves); K(s)=4096, chunk=128.
// ---------------------------------------------------------------------------
__global__ __launch_bounds__(512) void k4_mma(const float* __restrict__ enc) {
    extern __shared__ __align__(128) uint8_t sm[];
    const int tid = threadIdx.x, w = tid >> 5, lane = tid & 31;
    const int grp = lane >> 2, tig = lane & 3;
    const int wk = w & 7, sgrp = w >> 3;
    const int b = blockIdx.y;
    const int kb0 = blockIdx.x * 128;
    const int kW = kb0 + wk * 16;
    uint32_t sbase = smem_u32(sm);
    const float* encb = enc + (size_t)b * SS * K2;
    const __nv_bfloat16* Bh = g_w_h + (size_t)b * 64 * SS;
    const __nv_bfloat16* Bl = g_w_l + (size_t)b * 64 * SS;

    const int q0 = tid, q1 = tid + 512;
    const int l0q = q0 >> 4, ko0q = (q0 & 15) * 8;
    const int l1q = q1 >> 4, ko1q = (q1 & 15) * 8;

    {
        uint4 a = *(const uint4*)(Bh + (size_t)l0q * SS + ko0q);
        uint4 bq = *(const uint4*)(Bh + (size_t)l1q * SS + ko1q);
        uint4 cq = *(const uint4*)(Bl + (size_t)l0q * SS + ko0q);
        uint4 dq = *(const uint4*)(Bl + (size_t)l1q * SS + ko1q);
        *(uint4*)(sm + bofs(l0q, ko0q)) = a;
        *(uint4*)(sm + bofs(l1q, ko1q)) = bq;
        *(uint4*)(sm + 16384 + bofs(l0q, ko0q)) = cq;
        *(uint4*)(sm + 16384 + bofs(l1q, ko1q)) = dq;
    }
    __syncthreads();

    float d[8][4];
    #pragma unroll
    for (int i = 0; i < 8; i++) { d[i][0]=d[i][1]=d[i][2]=d[i][3]=0.f; }

    for (int c = 0; c < 32; c++) {
        int p = c & 1;
        uint4 ph0, ph1, pl0, pl1;
        if (c < 31) {
            int s1 = (c + 1) * 128;
            ph0 = *(const uint4*)(Bh + (size_t)l0q * SS + s1 + ko0q);
            ph1 = *(const uint4*)(Bh + (size_t)l1q * SS + s1 + ko1q);
            pl0 = *(const uint4*)(Bl + (size_t)l0q * SS + s1 + ko0q);
            pl1 = *(const uint4*)(Bl + (size_t)l1q * SS + s1 + ko1q);
        }
        #pragma unroll
        for (int ks2 = 0; ks2 < 4; ks2++) {
            int ks = ks2 * 2 + sgrp;
            int s0 = c * 128 + ks * 16;
            const float* ap = encb + (size_t)(s0 + tig * 2) * K2 + kW + grp;
            uint32_t ah[4], al[4];
            split2(ap[0],          ap[K2],           ah[0], al[0]);
            split2(ap[8],          ap[K2 + 8],       ah[1], al[1]);
            split2(ap[8 * K2],     ap[9 * K2],       ah[2], al[2]);
            split2(ap[8 * K2 + 8], ap[9 * K2 + 8],   ah[3], al[3]);
            int kol = ks * 16 + (lane & 8);
            #pragma unroll
            for (int np = 0; np < 4; np++) {
                int lr = np * 16 + (lane & 7) + ((lane >> 1) & 8);
                uint32_t addr = sbase + (uint32_t)p * 32768 + bofs(lr, kol);
                uint32_t bh4[4], bl4[4];
                ldmx4(bh4, addr);
                ldmx4(bl4, addr + 16384);
                mma_bf16(d[2*np],   ah, bh4[0], bh4[1]);
                mma_bf16(d[2*np],   al, bh4[0], bh4[1]);
                mma_bf16(d[2*np],   ah, bl4[0], bl4[1]);
                mma_bf16(d[2*np+1], ah, bh4[2], bh4[3]);
                mma_bf16(d[2*np+1], al, bh4[2], bh4[3]);
                mma_bf16(d[2*np+1], ah, bl4[2], bl4[3]);
            }
        }
        if (c < 31) {
            __syncthreads();
            uint32_t bo = (uint32_t)(p ^ 1) * 32768;
            *(uint4*)(sm + bo + bofs(l0q, ko0q)) = ph0;
            *(uint4*)(sm + bo + bofs(l1q, ko1q)) = ph1;
            *(uint4*)(sm + bo + 16384 + bofs(l0q, ko0q)) = pl0;
            *(uint4*)(sm + bo + 16384 + bofs(l1q, ko1q)) = pl1;
            __syncthreads();
        }
    }

    // reduce the two s-halves via smem, then emit bf16 hi/lo rows [l][k]
    __syncthreads();
    float* acc = (float*)sm;
    {
        int base = sgrp * 8192;
        #pragma unroll
        for (int nt = 0; nt < 8; nt++) {
            int li = nt * 8 + tig * 2;
            int kr = wk * 16 + grp;
            acc[base + li * 128 + kr]           = d[nt][0];
            acc[base + (li + 1) * 128 + kr]     = d[nt][1];
            acc[base + li * 128 + kr + 8]       = d[nt][2];
            acc[base + (li + 1) * 128 + kr + 8] = d[nt][3];
        }
    }
    __syncthreads();
    {
        int l = tid >> 3, kq = (tid & 7) * 16;
        const float* s0p = acc + l * 128 + kq;
        const float* s1p = acc + 8192 + l * 128 + kq;
        uint32_t hb[8], lb[8];
        #pragma unroll
        for (int j = 0; j < 8; j++) {
            float x0 = s0p[2 * j] + s1p[2 * j];
            float x1 = s0p[2 * j + 1] + s1p[2 * j + 1];
            split2(x0, x1, hb[j], lb[j]);
        }
        size_t ro = (size_t)(b * 64 + l) * K2 + kb0 + kq;
        *(uint4*)(g_c2_h + ro)     = make_uint4(hb[0], hb[1], hb[2], hb[3]);
        *(uint4*)(g_c2_h + ro + 8) = make_uint4(hb[4], hb[5], hb[6], hb[7]);
        *(uint4*)(g_c2_l + ro)     = make_uint4(lb[0], lb[1], lb[2], lb[3]);
        *(uint4*)(g_c2_l + ro + 8) = make_uint4(lb[4], lb[5], lb[6], lb[7]);
    }
}

// ---------------------------------------------------------------------------
// K5 (mma): out[m, h] = bias[h] + sum_k ctx2[m,k] * W[h,k]
// grid (32,4), 256thr; warp tile 16m x 32n; K=2048.
// ---------------------------------------------------------------------------
__global__ __launch_bounds__(256) void k5_mma(const float* __restrict__ W,
                                              const float* __restrict__ bias,
                                              float* __restrict__ out) {
    const int tid = threadIdx.x, w = tid >> 5, lane = tid & 31;
    const int grp = lane >> 2, tig = lane & 3;
    const int m0 = blockIdx.y * 128 + w * 16;
    const int n0 = blockIdx.x * 32;
    int mA = m0 + grp, mB = mA + 8;
    const uint32_t* a0h = (const uint32_t*)(g_c2_h + (size_t)mA * K2) + tig;
    const uint32_t* a0l = (const uint32_t*)(g_c2_l + (size_t)mA * K2) + tig;
    const uint32_t* a1h = (const uint32_t*)(g_c2_h + (size_t)mB * K2) + tig;
    const uint32_t* a1l = (const uint32_t*)(g_c2_l + (size_t)mB * K2) + tig;

    float d[4][4];
    #pragma unroll
    for (int i = 0; i < 4; i++) { d[i][0]=d[i][1]=d[i][2]=d[i][3]=0.f; }

    for (int k0 = 0; k0 < K2; k0 += 16) {
        int ku = k0 >> 1;
        uint32_t ah[4], al[4];
        ah[0] = a0h[ku];     al[0] = a0l[ku];
        ah[1] = a1h[ku];     al[1] = a1l[ku];
        ah[2] = a0h[ku + 4]; al[2] = a0l[ku + 4];
        ah[3] = a1h[ku + 4]; al[3] = a1l[ku + 4];
        #pragma unroll
        for (int nt = 0; nt < 4; nt++) {
            const float* wp = W + (size_t)(n0 + nt * 8 + grp) * K2 + k0 + 2 * tig;
            float2 u0 = *(const float2*)(wp);
            float2 u1 = *(const float2*)(wp + 8);
            uint32_t bh0, bl0, bh1, bl1;
            split2(u0.x, u0.y, bh0, bl0);
            split2(u1.x, u1.y, bh1, bl1);
            mma_bf16(d[nt], ah, bh0, bh1);
            mma_bf16(d[nt], al, bh0, bh1);
            mma_bf16(d[nt], ah, bl0, bl1);
        }
    }
    #pragma unroll
    for (int nt = 0; nt < 4; nt++) {
        int hp = n0 + nt * 8 + tig * 2;
        float2 bv = *(const float2*)(bias + hp);
        float2 o0 = {d[nt][0] + bv.x, d[nt][1] + bv.y};
        float2 o1 = {d[nt][2] + bv.x, d[nt][3] + bv.y};
        *(float2*)(out + (size_t)mA * HD + hp) = o0;
        *(float2*)(out + (size_t)mB * HD + hp) = o1;
    }
}

// ---------------------------------------------------------------------------
extern "C" void kernel_launch(void* const* d_in, const int* in_sizes, int n_in,
                              void* d_out, int out_size) {
    (void)in_sizes; (void)n_in; (void)out_size;
    const float* hidden = (const float*)d_in[0];
    const float* enc    = (const float*)d_in[1];
    const float* W      = (const float*)d_in[2];
    const float* bias   = (const float*)d_in[3];
    float* out_ctx = (float*)d_out;
    float* out_w   = (float*)d_out + (size_t)BB * LL * HD;

    static int attr_done = 0;
    cudaFuncSetAttribute(k2_mma, cudaFuncAttributeMaxDynamicSharedMemorySize, 65536);
    cudaFuncSetAttribute(k4_mma, cudaFuncAttributeMaxDynamicSharedMemorySize, 65536);
    (void)attr_done;

    k_bh<<<64, 256>>>(hidden, bias);
    k1_mma<<<dim3(32, 4), 256>>>(hidden, W);
    k2_mma<<<dim3(16, 8), 512, 65536>>>(enc);
    k3_softmax<<<512, 256>>>(out_w);
    k4_mma<<<dim3(16, 8), 512, 65536>>>(enc);
    k5_mma<<<dim3(32, 4), 256>>>(W, bias, out_ctx);
}